// round 10
// baseline (speedup 1.0000x reference)
#include <cuda_runtime.h>

// Banded attention |i-j|<=4: B=256, S=128, D=1024, H=16, HD=64, fp32.
// Grid 8192: one CTA (128 thr) per (b,h,half) -> 64 queries. K window (72
// clamped rows, 18.4KB) staged via cp.async; V from global (L2-resident).
// 16-lane subgroups (lane owns dims 4l..4l+3) handle adjacent query pairs
// over a shared 10-row window -> ~46 regs -> 10 CTAs/SM (40 warps).
// 4-step shuffle reduction, packed f32x2 FMA, single-pass online softmax.

constexpr int S_LEN   = 128;
constexpr int D_MODEL = 1024;
constexpr int THREADS = 128;
constexpr int QB      = 64;        // queries per CTA
constexpr int KROWS   = QB + 8;    // 72 staged rows (clamped)
constexpr int WROWS   = 10;

using u64 = unsigned long long;

__device__ __forceinline__ u64 f2_fma(u64 a, u64 b, u64 c) {
    u64 d; asm("fma.rn.f32x2 %0,%1,%2,%3;" : "=l"(d) : "l"(a), "l"(b), "l"(c)); return d;
}
__device__ __forceinline__ u64 f2_mul(u64 a, u64 b) {
    u64 d; asm("mul.rn.f32x2 %0,%1,%2;" : "=l"(d) : "l"(a), "l"(b)); return d;
}
__device__ __forceinline__ u64 f2_pack(float lo, float hi) {
    u64 d; asm("mov.b64 %0,{%1,%2};" : "=l"(d) : "f"(lo), "f"(hi)); return d;
}
__device__ __forceinline__ float2 f2_unpack(u64 a) {
    float lo, hi; asm("mov.b64 {%0,%1},%2;" : "=f"(lo), "=f"(hi) : "l"(a));
    return make_float2(lo, hi);
}
__device__ __forceinline__ void ld4(const float* __restrict__ p, u64& a, u64& b) {
    float4 f = *reinterpret_cast<const float4*>(p);
    a = f2_pack(f.x, f.y);
    b = f2_pack(f.z, f.w);
}
__device__ __forceinline__ void st4(float* __restrict__ p, u64 a, u64 b) {
    float2 lo = f2_unpack(a), hi = f2_unpack(b);
    *reinterpret_cast<float4*>(p) = make_float4(lo.x, lo.y, hi.x, hi.y);
}
__device__ __forceinline__ void cp_async16(unsigned s, const void* g) {
    asm volatile("cp.async.ca.shared.global [%0], [%1], 16;" :: "r"(s), "l"(g));
}

__global__ __launch_bounds__(THREADS, 10)
void band_attn_kernel(const float* __restrict__ q,
                      const float* __restrict__ k,
                      const float* __restrict__ v,
                      float* __restrict__ out)
{
    extern __shared__ float smem[];   // K window [72][64]
    float* ks = smem;

    const int tid   = threadIdx.x;
    const int cta   = blockIdx.x;     // 0..8191
    const int bh    = cta >> 1;
    const int half  = cta & 1;
    const int qbase = half * QB;
    const int b     = bh >> 4;
    const int h     = bh & 15;
    const size_t base = (size_t)b * S_LEN * D_MODEL + (size_t)h * 64;

    const float* kb = k   + base;
    const float* vb = v   + base;
    const float* qb = q   + base;
    float*       ob = out + base;

    // Stage K window: smem row r holds K[clamp(qbase-4+r)]. 1152 x 16B chunks.
    const unsigned ks_s = (unsigned)__cvta_generic_to_shared(ks);
    #pragma unroll
    for (int it = 0; it < 9; ++it) {
        int idx = it * THREADS + tid;       // 0..1151
        int row = idx >> 4;
        int c4  = idx & 15;
        int gr  = min(max(qbase - 4 + row, 0), S_LEN - 1);
        cp_async16(ks_s + (unsigned)(row * 64 + c4 * 4) * 4u,
                   kb + (size_t)gr * D_MODEL + c4 * 4);
    }
    asm volatile("cp.async.commit_group;");

    const int warp = tid >> 5;              // 0..3
    const int lane = tid & 31;
    const int g    = lane >> 4;             // subgroup 0..1
    const int l    = lane & 15;             // lane in subgroup
    const int c0   = 4 * l;                 // owned float4 chunk
    const u64 scale2 = f2_pack(0.125f, 0.125f);

    // Hoist t=0 Q loads to overlap the K stage.
    u64 q0[2], q1[2];
    {
        const int i0 = qbase + warp * 16 + g * 2;
        ld4(qb + (size_t)i0 * D_MODEL + c0,       q0[0], q0[1]);
        ld4(qb + (size_t)(i0 + 1) * D_MODEL + c0, q1[0], q1[1]);
        q0[0] = f2_mul(q0[0], scale2); q0[1] = f2_mul(q0[1], scale2);
        q1[0] = f2_mul(q1[0], scale2); q1[1] = f2_mul(q1[1], scale2);
    }

    asm volatile("cp.async.wait_group 0;");
    __syncthreads();

    #pragma unroll 1
    for (int t = 0; t < 4; ++t) {
        const int il = warp * 16 + t * 4 + g * 2;   // CTA-local even query
        const int i0 = qbase + il;
        const int i1 = i0 + 1;

        if (t > 0) {
            ld4(qb + (size_t)i0 * D_MODEL + c0, q0[0], q0[1]);
            ld4(qb + (size_t)i1 * D_MODEL + c0, q1[0], q1[1]);
            q0[0] = f2_mul(q0[0], scale2); q0[1] = f2_mul(q0[1], scale2);
            q1[0] = f2_mul(q1[0], scale2); q1[1] = f2_mul(q1[1], scale2);
        }

        float den0 = 0.f, den1 = 0.f;
        u64 acc0[2] = {0, 0};
        u64 acc1[2] = {0, 0};

        #pragma unroll
        for (int r = 0; r < WROWS; ++r) {
            const int j = i0 - 4 + r;

            u64 kv[2];
            ld4(ks + (il + r) * 64 + c0, kv[0], kv[1]);   // LDS.128

            u64 a0 = f2_mul(q0[0], kv[0]);
            a0 = f2_fma(q0[1], kv[1], a0);
            u64 a1 = f2_mul(q1[0], kv[0]);
            a1 = f2_fma(q1[1], kv[1], a1);

            float2 s0 = f2_unpack(a0);
            float2 s1 = f2_unpack(a1);
            float p0 = s0.x + s0.y;
            float p1 = s1.x + s1.y;

            p0 += __shfl_xor_sync(0xffffffffu, p0, 1);
            p0 += __shfl_xor_sync(0xffffffffu, p0, 2);
            p0 += __shfl_xor_sync(0xffffffffu, p0, 4);
            p0 += __shfl_xor_sync(0xffffffffu, p0, 8);
            p1 += __shfl_xor_sync(0xffffffffu, p1, 1);
            p1 += __shfl_xor_sync(0xffffffffu, p1, 2);
            p1 += __shfl_xor_sync(0xffffffffu, p1, 4);
            p1 += __shfl_xor_sync(0xffffffffu, p1, 8);

            const bool in_seq = (j >= 0) && (j < S_LEN);
            const float e0 = (in_seq && r <= 8) ? __expf(p0) : 0.f;
            const float e1 = (in_seq && r >= 1) ? __expf(p1) : 0.f;
            den0 += e0;
            den1 += e1;

            const int jc = min(max(j, 0), S_LEN - 1);
            u64 vv[2];
            ld4(vb + (size_t)jc * D_MODEL + c0, vv[0], vv[1]);  // LDG.128

            const u64 e0p = f2_pack(e0, e0);
            const u64 e1p = f2_pack(e1, e1);
            acc0[0] = f2_fma(e0p, vv[0], acc0[0]);
            acc0[1] = f2_fma(e0p, vv[1], acc0[1]);
            acc1[0] = f2_fma(e1p, vv[0], acc1[0]);
            acc1[1] = f2_fma(e1p, vv[1], acc1[1]);
        }

        const float inv0 = 1.0f / den0;
        const float inv1 = 1.0f / den1;
        const u64 i0p = f2_pack(inv0, inv0);
        const u64 i1p = f2_pack(inv1, inv1);
        st4(ob + (size_t)i0 * D_MODEL + c0,
            f2_mul(acc0[0], i0p), f2_mul(acc0[1], i0p));
        st4(ob + (size_t)i1 * D_MODEL + c0,
            f2_mul(acc1[0], i1p), f2_mul(acc1[1], i1p));
    }
}

extern "C" void kernel_launch(void* const* d_in, const int* in_sizes, int n_in,
                              void* d_out, int out_size)
{
    const float* q = (const float*)d_in[0];
    const float* k = (const float*)d_in[1];
    const float* v = (const float*)d_in[2];
    float* out = (float*)d_out;

    const int smem_bytes = KROWS * 64 * (int)sizeof(float);  // 18432
    cudaFuncSetAttribute(band_attn_kernel,
                         cudaFuncAttributeMaxDynamicSharedMemorySize, smem_bytes);

    const int n_cta = 256 * 16 * 2;  // B * H * 2 halves
    band_attn_kernel<<<n_cta, THREADS, smem_bytes>>>(q, k, v, out);
}